// round 11
// baseline (speedup 1.0000x reference)
#include <cuda_runtime.h>
#include <cstdint>

// Problem constants
#define BB 128
#define DD 128
#define TT 2048
#define CC 64
#define TILE_T 512
#define NTILES 4
#define DCH 32                    // d per chunk
#define NCH 4
#define NPAIR 16                  // bf16x2 words per row per chunk
#define THREADS 512
#define NWARP 16
#define PITCH32 17                // u32 pitch per row (16 + 1)
#define GRID 512
#define NREP 8
#define ZROW (TILE_T * PITCH32)   // zero-row word index (8704)
#define PRE_N 576                 // 512 rows + <=64 pads

// Scratch (allocation-free; self-reset each run so graph replays are identical)
__device__ float        g_S[NREP][CC * DD];
__device__ float        g_loss;
__device__ int          g_count[CC];
__device__ unsigned int g_done;

// smem layout (bytes)
#define SM_TILE   0
#define SM_TILE_B ((ZROW + NPAIR) * 4)     // 34880
#define SM_PRE    34896
#define SM_HIST   (SM_PRE + PRE_N * 4)     // 37200
#define SM_START  (SM_HIST + CC * 4)
#define SM_CUR    (SM_START + CC * 4)
#define SM_WRED   (SM_CUR + CC * 4)
#define SM_WTOT   (SM_WRED + NWARP * 4)
#define SM_TICK   (SM_WTOT + 8)
#define SM_TOTAL  (SM_TICK + 8)

__global__ __launch_bounds__(THREADS, 2)
void cl_fused_kernel(const float* __restrict__ feature,
                     const int* __restrict__ label,
                     const float* __restrict__ centers,
                     float* __restrict__ out) {
    extern __shared__ char sm[];
    uint32_t*     tile32 = (uint32_t*)(sm + SM_TILE);
    uint32_t*     pre    = (uint32_t*)(sm + SM_PRE);
    int*          hist   = (int*)(sm + SM_HIST);
    int*          starts = (int*)(sm + SM_START);
    int*          cursor = (int*)(sm + SM_CUR);
    float*        wred   = (float*)(sm + SM_WRED);
    int*          wtot   = (int*)(sm + SM_WTOT);
    unsigned int* tick   = (unsigned int*)(sm + SM_TICK);

    const int tid  = threadIdx.x;
    const int lane = tid & 31;
    const int wid  = tid >> 5;
    const int b    = blockIdx.x >> 2;
    const int t0   = (blockIdx.x & 3) * TILE_T;
    const int rep  = blockIdx.x & (NREP - 1);

    const int t4 = tid & 127;          // float4 slot along t
    const int dg = tid >> 7;           // 0..3 -> pair p = dg + 4k
    const int kk = (t4 >> 3) & 3;      // store bank key

    // Label + full-chunk prefetch FIRST (latency hides behind prologue).
    const int myl = label[b * TT + t0 + tid] & (CC - 1);

    const float4* f4b = (const float4*)feature
        + ((long long)b * DD) * (TT / 4) + (t0 >> 2) + t4;
    float4 va[4], vb[4];               // d-pair rows: even (va) / odd (vb)
    #pragma unroll
    for (int k = 0; k < 4; k++) {
        int p = dg + 4 * k;
        va[k] = f4b[(2 * p)     * (TT / 4)];
        vb[k] = f4b[(2 * p + 1) * (TT / 4)];
    }

    // ---- Prologue: histogram, even-padded scan, descriptor scatter ----
    if (tid < CC) hist[tid] = 0;
    if (tid < NPAIR) tile32[ZROW + tid] = 0u;       // zero row (never stored to)
    __syncthreads();

    atomicAdd(&hist[myl], 1);
    __syncthreads();

    {   // exclusive scan of even-padded class sizes (warps 0/1 + carry)
        int m  = (tid < CC) ? hist[tid] : 0;
        int p2 = (m + 1) & ~1;
        int incl = p2;
        #pragma unroll
        for (int o = 1; o < 32; o <<= 1) {
            int n = __shfl_up_sync(0xffffffffu, incl, o);
            if (lane >= o) incl += n;
        }
        if (wid < 2 && lane == 31) wtot[wid] = incl;
        __syncthreads();
        if (tid < CC) {
            int st = incl - p2 + (wid == 1 ? wtot[0] : 0);
            starts[tid] = st;
            cursor[tid] = st;
        }
        __syncthreads();
    }

    {   // scatter: desc = (t*17)<<4 | bankkey(t);  pad odd classes -> zero row
        int pos = atomicAdd(&cursor[myl], 1);
        pre[pos] = ((unsigned)(tid * PITCH32) << 4) | (unsigned)((tid >> 5) & 3);
        if (tid < CC) {
            int m = hist[tid];
            if (m & 1) pre[starts[tid] + m] = (unsigned)ZROW << 4;
            atomicAdd(&g_count[tid], m);
        }
    }

    float sumsq = 0.0f;
    const int lanelow = lane & 15;
    const int half    = lane >> 4;
    const int d0      = 2 * lanelow;

    // ---- Main loop over 4 d-chunks ----
    for (int ch = 0; ch < NCH; ch++) {
        __syncthreads();   // tile free (previous gather done)

        // Pack f32 pairs -> bf16x2, store to conflict-free swizzled tile.
        // word = (4*t4+j)*17 + (p ^ kk): proven all-32-lane bank-distinct.
        #pragma unroll
        for (int k = 0; k < 4; k++) {
            int p    = dg + 4 * k;
            int base = t4 * (4 * PITCH32) + (p ^ kk);
            float4 a = va[k], b4 = vb[k];
            uint32_t u0, u1, u2, u3;   // hi = odd d, lo = even d
            asm("cvt.rn.bf16x2.f32 %0, %1, %2;" : "=r"(u0) : "f"(b4.x), "f"(a.x));
            asm("cvt.rn.bf16x2.f32 %0, %1, %2;" : "=r"(u1) : "f"(b4.y), "f"(a.y));
            asm("cvt.rn.bf16x2.f32 %0, %1, %2;" : "=r"(u2) : "f"(b4.z), "f"(a.z));
            asm("cvt.rn.bf16x2.f32 %0, %1, %2;" : "=r"(u3) : "f"(b4.w), "f"(a.w));
            tile32[base]               = u0;
            tile32[base + PITCH32]     = u1;
            tile32[base + 2 * PITCH32] = u2;
            tile32[base + 3 * PITCH32] = u3;
            sumsq = fmaf(a.x, a.x, sumsq);  sumsq = fmaf(a.y, a.y, sumsq);
            sumsq = fmaf(a.z, a.z, sumsq);  sumsq = fmaf(a.w, a.w, sumsq);
            sumsq = fmaf(b4.x, b4.x, sumsq); sumsq = fmaf(b4.y, b4.y, sumsq);
            sumsq = fmaf(b4.z, b4.z, sumsq); sumsq = fmaf(b4.w, b4.w, sumsq);
        }

        // Prefetch NEXT chunk before the barrier: issue-to-use distance =
        // barrier wait + entire gather phase.
        if (ch < NCH - 1) {
            const float4* f4n = f4b + (long long)((ch + 1) * DCH) * (TT / 4);
            #pragma unroll
            for (int k = 0; k < 4; k++) {
                int p = dg + 4 * k;
                va[k] = f4n[(2 * p)     * (TT / 4)];
                vb[k] = f4n[(2 * p + 1) * (TT / 4)];
            }
        }
        __syncthreads();   // tile ready

        // Gather: 2 sorted rows per LDS (half-warps), lane covers d-pair.
        // Per iteration: 1 desc LDS + 1 tile LDS serve 64 elements.
        float* gS = &g_S[rep][ch * DCH + d0];
        for (int c = wid; c < CC; c += NWARP) {
            const int m = hist[c];
            if (m == 0) continue;
            const int st = starts[c];
            const int p2 = (m + 1) & ~1;
            float a0 = 0.0f, a1 = 0.0f;
            for (int i = 0; i < p2; i += 2) {
                unsigned x = pre[st + i + half];
                unsigned u = tile32[(x >> 4) + ((unsigned)lanelow ^ (x & 15u))];
                a0 += __uint_as_float(u << 16);          // even d
                a1 += __uint_as_float(u & 0xFFFF0000u);  // odd d
            }
            atomicAdd(gS + c * DD,     a0);   // half-warps: deg-2 addr sharing, correct
            atomicAdd(gS + c * DD + 1, a1);
        }
    }

    // sumsq reduction: lane -> warp -> block -> global
    #pragma unroll
    for (int o = 16; o > 0; o >>= 1)
        sumsq += __shfl_xor_sync(0xffffffffu, sumsq, o);
    if (lane == 0) wred[wid] = sumsq;
    __syncthreads();
    if (tid == 0) {
        float s = 0.0f;
        #pragma unroll
        for (int w = 0; w < NWARP; w++) s += wred[w];
        atomicAdd(&g_loss, s);
    }

    // ---- Last-block finalize ----
    __threadfence();
    if (tid == 0) tick[0] = atomicAdd(&g_done, 1u);
    __syncthreads();
    if (tick[0] == GRID - 1) {
        __threadfence();
        float part = 0.0f;
        for (int i = tid; i < CC * DD; i += THREADS) {
            float s = 0.0f;
            #pragma unroll
            for (int r = 0; r < NREP; r++) { s += g_S[r][i]; g_S[r][i] = 0.0f; }
            int   c   = i >> 7;
            int   cnt = g_count[c];
            float cen = centers[i];
            out[1 + i] = (cnt > 0) ? (cen - __fdividef(s, (float)cnt)) : 0.0f;
            part += cen * ((float)cnt * cen - 2.0f * s);   // loss cross terms
        }
        #pragma unroll
        for (int o = 16; o > 0; o >>= 1)
            part += __shfl_xor_sync(0xffffffffu, part, o);
        if (lane == 0) wred[wid] = part;
        __syncthreads();
        if (tid == 0) {
            float t = 0.0f;
            #pragma unroll
            for (int w = 0; w < NWARP; w++) t += wred[w];
            out[0] = (g_loss + t) / 33554432.0f;           // / (N*D)
            g_loss = 0.0f; g_done = 0u;
        }
        if (tid < CC) g_count[tid] = 0;
    }
}

extern "C" void kernel_launch(void* const* d_in, const int* in_sizes, int n_in,
                              void* d_out, int out_size) {
    const float* feature = 0;
    const int*   label   = 0;
    const float* centers = 0;
    for (int i = 0; i < n_in; i++) {
        if (in_sizes[i] == BB * DD * TT)      feature = (const float*)d_in[i];
        else if (in_sizes[i] == BB * TT)      label   = (const int*)d_in[i];
        else if (in_sizes[i] == CC * DD)      centers = (const float*)d_in[i];
    }
    float* out = (float*)d_out;
    (void)out_size;

    cudaFuncSetAttribute(cl_fused_kernel,
                         cudaFuncAttributeMaxDynamicSharedMemorySize, SM_TOTAL);

    cl_fused_kernel<<<GRID, THREADS, SM_TOTAL>>>(feature, label, centers, out);
}

// round 13
// speedup vs baseline: 1.0050x; 1.0050x over previous
#include <cuda_runtime.h>
#include <cstdint>

// Problem constants
#define BB 128
#define DD 128
#define TT 2048
#define CC 64
#define TILE_T 512
#define DCH 32                    // d per chunk
#define NCH 4
#define THREADS 512
#define NWARP 16
#define PITCH32 17                // u32 pitch per row
#define GRID 512
#define NREP 8
#define ZROW (TILE_T * PITCH32)   // zero-row word index within a buffer (8704)
#define BUFW (ZROW + 16)          // words per buffer (8720)
#define PRE_N 576                 // 512 rows + <=64 pads

// Scratch (allocation-free; self-reset each run so graph replays are identical)
__device__ float        g_S[NREP][CC * DD];
__device__ float        g_loss;
__device__ int          g_count[CC];
__device__ unsigned int g_done;

// smem layout (bytes)
#define SM_BUF0   0
#define SM_BUF1   (BUFW * 4)               // 34880
#define SM_PRE    (2 * BUFW * 4)           // 69760
#define SM_HIST   (SM_PRE + PRE_N * 4)     // 72064
#define SM_START  (SM_HIST + CC * 4)
#define SM_CUR    (SM_START + CC * 4)
#define SM_WRED   (SM_CUR + CC * 4)
#define SM_WTOT   (SM_WRED + NWARP * 4)
#define SM_TICK   (SM_WTOT + 8)
#define SM_TOTAL  (SM_TICK + 8)

__global__ __launch_bounds__(THREADS, 2)
void cl_fused_kernel(const float* __restrict__ feature,
                     const int* __restrict__ label,
                     const float* __restrict__ centers,
                     float* __restrict__ out) {
    extern __shared__ char sm[];
    uint32_t*     buf0   = (uint32_t*)(sm + SM_BUF0);
    uint32_t*     buf1   = (uint32_t*)(sm + SM_BUF1);
    uint32_t*     pre    = (uint32_t*)(sm + SM_PRE);
    int*          hist   = (int*)(sm + SM_HIST);
    int*          starts = (int*)(sm + SM_START);
    int*          cursor = (int*)(sm + SM_CUR);
    float*        wred   = (float*)(sm + SM_WRED);
    int*          wtot   = (int*)(sm + SM_WTOT);
    unsigned int* tick   = (unsigned int*)(sm + SM_TICK);

    const int tid  = threadIdx.x;
    const int lane = tid & 31;
    const int wid  = tid >> 5;
    const int b    = blockIdx.x >> 2;
    const int t0   = (blockIdx.x & 3) * TILE_T;
    const int rep  = blockIdx.x & (NREP - 1);

    // Producer geometry (tid < 256): t4p fixed, pair p = dg2 + 2k
    const int t4p = tid & 127;
    const int dg2 = (tid >> 7) & 1;
    const int kk  = (t4p >> 3) & 3;        // store bank key (R11-validated)

    // ---- Prologue (all threads): labels, histogram, even-padded scan, scatter ----
    const int myl = label[b * TT + t0 + tid] & (CC - 1);   // tid == row

    if (tid < CC) hist[tid] = 0;
    if (tid < 16) { buf0[ZROW + tid] = 0u; buf1[ZROW + tid] = 0u; }
    __syncthreads();

    atomicAdd(&hist[myl], 1);
    __syncthreads();

    {   // exclusive scan of even-padded class sizes (warps 0/1 + carry)
        int m  = (tid < CC) ? hist[tid] : 0;
        int p2 = (m + 1) & ~1;
        int incl = p2;
        #pragma unroll
        for (int o = 1; o < 32; o <<= 1) {
            int n = __shfl_up_sync(0xffffffffu, incl, o);
            if (lane >= o) incl += n;
        }
        if (wid < 2 && lane == 31) wtot[wid] = incl;
        __syncthreads();
        if (tid < CC) {
            int st = incl - p2 + (wid == 1 ? wtot[0] : 0);
            starts[tid] = st;
            cursor[tid] = st;
        }
        __syncthreads();
    }

    {   // scatter: desc = (t*17)<<4 | bankkey(t); pad odd classes -> zero row
        int pos = atomicAdd(&cursor[myl], 1);
        pre[pos] = ((unsigned)(tid * PITCH32) << 4) | (unsigned)((tid >> 5) & 3);
        if (tid < CC) {
            int m = hist[tid];
            if (m & 1) pre[starts[tid] + m] = (unsigned)ZROW << 4;
            atomicAdd(&g_count[tid], m);
        }
    }
    __syncthreads();   // pre[] ready for consumers

    float sumsq = 0.0f;
    const int lanelow = lane & 15;
    const int half    = lane >> 4;
    const int d0      = 2 * lanelow;
    const float4* f40 = (const float4*)feature;

    // ---- Software pipeline: producers fill buf[it&1], consumers drain buf[(it-1)&1]
    for (int it = 0; it <= NCH; it++) {
        if (wid < 8) {
            // ---------------- PRODUCER: load chunk 'it', pack bf16x2, store ----
            if (it < NCH) {
                uint32_t* buf = (it & 1) ? buf1 : buf0;
                const float4* f4 = f40
                    + ((long long)b * DD + it * DCH) * (TT / 4) + (t0 >> 2) + t4p;
                #pragma unroll
                for (int h = 0; h < 2; h++) {
                    float4 A[4], B[4];
                    #pragma unroll
                    for (int k = 0; k < 4; k++) {
                        int p = dg2 + 2 * (4 * h + k);
                        A[k] = f4[(2 * p)     * (TT / 4)];
                        B[k] = f4[(2 * p + 1) * (TT / 4)];
                    }
                    #pragma unroll
                    for (int k = 0; k < 4; k++) {
                        int p    = dg2 + 2 * (4 * h + k);
                        int base = t4p * (4 * PITCH32) + (p ^ kk);
                        uint32_t u0, u1, u2, u3;   // hi = odd d, lo = even d
                        asm("cvt.rn.bf16x2.f32 %0, %1, %2;" : "=r"(u0) : "f"(B[k].x), "f"(A[k].x));
                        asm("cvt.rn.bf16x2.f32 %0, %1, %2;" : "=r"(u1) : "f"(B[k].y), "f"(A[k].y));
                        asm("cvt.rn.bf16x2.f32 %0, %1, %2;" : "=r"(u2) : "f"(B[k].z), "f"(A[k].z));
                        asm("cvt.rn.bf16x2.f32 %0, %1, %2;" : "=r"(u3) : "f"(B[k].w), "f"(A[k].w));
                        buf[base]               = u0;
                        buf[base + PITCH32]     = u1;
                        buf[base + 2 * PITCH32] = u2;
                        buf[base + 3 * PITCH32] = u3;
                        sumsq = fmaf(A[k].x, A[k].x, sumsq); sumsq = fmaf(A[k].y, A[k].y, sumsq);
                        sumsq = fmaf(A[k].z, A[k].z, sumsq); sumsq = fmaf(A[k].w, A[k].w, sumsq);
                        sumsq = fmaf(B[k].x, B[k].x, sumsq); sumsq = fmaf(B[k].y, B[k].y, sumsq);
                        sumsq = fmaf(B[k].z, B[k].z, sumsq); sumsq = fmaf(B[k].w, B[k].w, sumsq);
                    }
                }
            }
        } else {
            // ---------------- CONSUMER: gather chunk 'it-1' ----
            if (it >= 1) {
                const int ch = it - 1;
                const uint32_t* buf = (ch & 1) ? buf1 : buf0;
                float* gS = &g_S[rep][ch * DCH + d0];
                for (int c = wid - 8; c < CC; c += 8) {
                    const int m = hist[c];
                    if (m == 0) continue;
                    const int st = starts[c];
                    const int p2 = (m + 1) & ~1;
                    float a0 = 0.0f, a1 = 0.0f;
                    for (int i = 0; i < p2; i += 2) {
                        unsigned x = pre[st + i + half];
                        unsigned u = buf[(x >> 4) + ((unsigned)lanelow ^ (x & 15u))];
                        a0 += __uint_as_float(u << 16);          // even d
                        a1 += __uint_as_float(u & 0xFFFF0000u);  // odd d
                    }
                    atomicAdd(gS + c * DD,     a0);
                    atomicAdd(gS + c * DD + 1, a1);
                }
            }
        }
        __syncthreads();   // retire interval: buf[it&1] full, buf[(it-1)&1] free
    }

    // sumsq reduction: lane -> warp -> block -> global (consumers contribute 0)
    #pragma unroll
    for (int o = 16; o > 0; o >>= 1)
        sumsq += __shfl_xor_sync(0xffffffffu, sumsq, o);
    if (lane == 0) wred[wid] = sumsq;
    __syncthreads();
    if (tid == 0) {
        float s = 0.0f;
        #pragma unroll
        for (int w = 0; w < NWARP; w++) s += wred[w];
        atomicAdd(&g_loss, s);
    }

    // ---- Last-block finalize ----
    __threadfence();
    if (tid == 0) tick[0] = atomicAdd(&g_done, 1u);
    __syncthreads();
    if (tick[0] == GRID - 1) {
        __threadfence();
        float part = 0.0f;
        for (int i = tid; i < CC * DD; i += THREADS) {
            float s = 0.0f;
            #pragma unroll
            for (int r = 0; r < NREP; r++) { s += g_S[r][i]; g_S[r][i] = 0.0f; }
            int   c   = i >> 7;
            int   cnt = g_count[c];
            float cen = centers[i];
            out[1 + i] = (cnt > 0) ? (cen - __fdividef(s, (float)cnt)) : 0.0f;
            part += cen * ((float)cnt * cen - 2.0f * s);   // loss cross terms
        }
        #pragma unroll
        for (int o = 16; o > 0; o >>= 1)
            part += __shfl_xor_sync(0xffffffffu, part, o);
        if (lane == 0) wred[wid] = part;
        __syncthreads();
        if (tid == 0) {
            float t = 0.0f;
            #pragma unroll
            for (int w = 0; w < NWARP; w++) t += wred[w];
            out[0] = (g_loss + t) / 33554432.0f;           // / (N*D)
            g_loss = 0.0f; g_done = 0u;
        }
        if (tid < CC) g_count[tid] = 0;
    }
}

extern "C" void kernel_launch(void* const* d_in, const int* in_sizes, int n_in,
                              void* d_out, int out_size) {
    const float* feature = 0;
    const int*   label   = 0;
    const float* centers = 0;
    for (int i = 0; i < n_in; i++) {
        if (in_sizes[i] == BB * DD * TT)      feature = (const float*)d_in[i];
        else if (in_sizes[i] == BB * TT)      label   = (const int*)d_in[i];
        else if (in_sizes[i] == CC * DD)      centers = (const float*)d_in[i];
    }
    float* out = (float*)d_out;
    (void)out_size;

    cudaFuncSetAttribute(cl_fused_kernel,
                         cudaFuncAttributeMaxDynamicSharedMemorySize, SM_TOTAL);

    cl_fused_kernel<<<GRID, THREADS, SM_TOTAL>>>(feature, label, centers, out);
}

// round 14
// speedup vs baseline: 1.0419x; 1.0367x over previous
#include <cuda_runtime.h>
#include <cstdint>

// Problem constants
#define BB 128
#define DD 128
#define TT 2048
#define CC 64
#define TILE_T 512
#define DCH 32                    // d per chunk
#define NCH 4
#define THREADS 512
#define NWARP 16
#define NPROD 4                   // producer warps; consumers = 12
#define NCONS 12
#define PITCH32 17                // u32 pitch per row
#define GRID 512
#define NREP 8
#define ZROW (TILE_T * PITCH32)   // zero-row word index within a buffer (8704)
#define BUFW (ZROW + 16)          // words per buffer (8720)
#define PRE_N 704                 // 512 rows + <=64*3 pads

// Scratch (allocation-free; self-reset each run so graph replays are identical)
__device__ float        g_S[NREP][CC * DD];
__device__ float        g_loss;
__device__ int          g_count[CC];
__device__ unsigned int g_done;

// smem layout (bytes)
#define SM_BUF0   0
#define SM_BUF1   (BUFW * 4)               // 34880
#define SM_PRE    (2 * BUFW * 4)           // 69760
#define SM_HIST   (SM_PRE + PRE_N * 4)     // 72576
#define SM_START  (SM_HIST + CC * 4)
#define SM_CUR    (SM_START + CC * 4)
#define SM_WRED   (SM_CUR + CC * 4)
#define SM_WTOT   (SM_WRED + NWARP * 4)
#define SM_TICK   (SM_WTOT + 8)
#define SM_TOTAL  (SM_TICK + 16)

__global__ __launch_bounds__(THREADS, 2)
void cl_fused_kernel(const float* __restrict__ feature,
                     const int* __restrict__ label,
                     const float* __restrict__ centers,
                     float* __restrict__ out) {
    extern __shared__ char sm[];
    uint32_t*     buf0   = (uint32_t*)(sm + SM_BUF0);
    uint32_t*     buf1   = (uint32_t*)(sm + SM_BUF1);
    uint32_t*     pre    = (uint32_t*)(sm + SM_PRE);
    int*          hist   = (int*)(sm + SM_HIST);
    int*          starts = (int*)(sm + SM_START);
    int*          cursor = (int*)(sm + SM_CUR);
    float*        wred   = (float*)(sm + SM_WRED);
    int*          wtot   = (int*)(sm + SM_WTOT);
    unsigned int* tick   = (unsigned int*)(sm + SM_TICK);

    const int tid  = threadIdx.x;
    const int lane = tid & 31;
    const int wid  = tid >> 5;
    const int b    = blockIdx.x >> 2;
    const int t0   = (blockIdx.x & 3) * TILE_T;
    const int rep  = blockIdx.x & (NREP - 1);

    // ---- Prologue (all threads): labels, histogram, 4-padded scan, scatter ----
    const int myl = label[b * TT + t0 + tid] & (CC - 1);   // tid == row

    if (tid < CC) hist[tid] = 0;
    if (tid < 16) { buf0[ZROW + tid] = 0u; buf1[ZROW + tid] = 0u; }
    __syncthreads();

    atomicAdd(&hist[myl], 1);
    __syncthreads();

    {   // exclusive scan of 4-padded class sizes (warps 0/1 + carry)
        int m  = (tid < CC) ? hist[tid] : 0;
        int p4 = (m + 3) & ~3;
        int incl = p4;
        #pragma unroll
        for (int o = 1; o < 32; o <<= 1) {
            int n = __shfl_up_sync(0xffffffffu, incl, o);
            if (lane >= o) incl += n;
        }
        if (wid < 2 && lane == 31) wtot[wid] = incl;
        __syncthreads();
        if (tid < CC) {
            int st = incl - p4 + (wid == 1 ? wtot[0] : 0);
            starts[tid] = st;
            cursor[tid] = st;
        }
        __syncthreads();
    }

    {   // scatter: desc = (t*17)<<4 | bankkey(t); pads -> zero-row desc
        int pos = atomicAdd(&cursor[myl], 1);
        pre[pos] = ((unsigned)(tid * PITCH32) << 4) | (unsigned)((tid >> 5) & 3);
        if (tid < CC) {
            int m  = hist[tid];
            int st = starts[tid];
            int p4 = (m + 3) & ~3;
            for (int k = m; k < p4; k++) pre[st + k] = (unsigned)ZROW << 4;
            atomicAdd(&g_count[tid], m);
        }
    }
    __syncthreads();   // pre[] ready

    float sumsq = 0.0f;
    const int lanelow = lane & 15;
    const int half    = lane >> 4;
    const float4* f40 = (const float4*)feature;

    // ---- Pipeline: 4 producer warps fill buf[it&1]; 12 consumers drain buf[(it-1)&1]
    for (int it = 0; it <= NCH; it++) {
        if (wid < NPROD) {
            // -------- PRODUCER (tid 0..127): t4 = tid, all 16 d-pairs --------
            if (it < NCH) {
                uint32_t* buf = (it & 1) ? buf1 : buf0;
                const int t4 = tid;                        // 0..127
                const int kk = (t4 >> 3) & 3;
                const float4* f4 = f40
                    + ((long long)b * DD + it * DCH) * (TT / 4) + (t0 >> 2) + t4;
                #pragma unroll
                for (int h = 0; h < 4; h++) {              // 4 batches x 4 pairs
                    float4 A[4], B[4];
                    #pragma unroll
                    for (int j = 0; j < 4; j++) {          // batch: 8 LDG.128 in flight
                        int p = h * 4 + j;
                        A[j] = f4[(2 * p)     * (TT / 4)];
                        B[j] = f4[(2 * p + 1) * (TT / 4)];
                    }
                    #pragma unroll
                    for (int j = 0; j < 4; j++) {
                        int p    = h * 4 + j;
                        int base = t4 * (4 * PITCH32) + (p ^ kk);
                        uint32_t u0, u1, u2, u3;           // hi = odd d, lo = even d
                        asm("cvt.rn.bf16x2.f32 %0, %1, %2;" : "=r"(u0) : "f"(B[j].x), "f"(A[j].x));
                        asm("cvt.rn.bf16x2.f32 %0, %1, %2;" : "=r"(u1) : "f"(B[j].y), "f"(A[j].y));
                        asm("cvt.rn.bf16x2.f32 %0, %1, %2;" : "=r"(u2) : "f"(B[j].z), "f"(A[j].z));
                        asm("cvt.rn.bf16x2.f32 %0, %1, %2;" : "=r"(u3) : "f"(B[j].w), "f"(A[j].w));
                        buf[base]               = u0;
                        buf[base + PITCH32]     = u1;
                        buf[base + 2 * PITCH32] = u2;
                        buf[base + 3 * PITCH32] = u3;
                        sumsq = fmaf(A[j].x, A[j].x, sumsq); sumsq = fmaf(A[j].y, A[j].y, sumsq);
                        sumsq = fmaf(A[j].z, A[j].z, sumsq); sumsq = fmaf(A[j].w, A[j].w, sumsq);
                        sumsq = fmaf(B[j].x, B[j].x, sumsq); sumsq = fmaf(B[j].y, B[j].y, sumsq);
                        sumsq = fmaf(B[j].z, B[j].z, sumsq); sumsq = fmaf(B[j].w, B[j].w, sumsq);
                    }
                }
            }
        } else {
            // -------- CONSUMER: gather chunk it-1 (4 rows/iter, 4 acc chains) ----
            if (it >= 1) {
                const int ch = it - 1;
                const uint32_t* buf = (ch & 1) ? buf1 : buf0;
                float* gS = &g_S[rep][ch * DCH + 2 * lanelow];
                for (int c = wid - NPROD; c < CC; c += NCONS) {
                    const int m = hist[c];
                    if (m == 0) continue;
                    const int st = starts[c];
                    const int p4 = (m + 3) & ~3;
                    float a00 = 0.0f, a01 = 0.0f, a10 = 0.0f, a11 = 0.0f;
                    for (int i = 0; i < p4; i += 4) {
                        // lanes 0-15 rows i,i+1; lanes 16-31 rows i+2,i+3
                        uint2 dd = *(const uint2*)&pre[st + i + 2 * half];
                        unsigned u0 = buf[(dd.x >> 4) + ((unsigned)lanelow ^ (dd.x & 15u))];
                        unsigned u1 = buf[(dd.y >> 4) + ((unsigned)lanelow ^ (dd.y & 15u))];
                        a00 += __uint_as_float(u0 << 16);           // even d
                        a01 += __uint_as_float(u0 & 0xFFFF0000u);   // odd d
                        a10 += __uint_as_float(u1 << 16);
                        a11 += __uint_as_float(u1 & 0xFFFF0000u);
                    }
                    float aE = a00 + a10, aO = a01 + a11;
                    aE += __shfl_xor_sync(0xffffffffu, aE, 16);     // combine halves
                    aO += __shfl_xor_sync(0xffffffffu, aO, 16);
                    if (half == 0) {                                 // one atomic set
                        atomicAdd(gS + c * DD,     aE);
                        atomicAdd(gS + c * DD + 1, aO);
                    }
                }
            }
        }
        __syncthreads();   // retire interval: buf[it&1] full, buf[(it-1)&1] free
    }

    // sumsq reduction: lane -> warp -> block -> global (consumers contribute 0)
    #pragma unroll
    for (int o = 16; o > 0; o >>= 1)
        sumsq += __shfl_xor_sync(0xffffffffu, sumsq, o);
    if (lane == 0) wred[wid] = sumsq;
    __syncthreads();
    if (tid == 0) {
        float s = 0.0f;
        #pragma unroll
        for (int w = 0; w < NWARP; w++) s += wred[w];
        atomicAdd(&g_loss, s);
    }

    // ---- Last-block finalize ----
    __threadfence();
    if (tid == 0) tick[0] = atomicAdd(&g_done, 1u);
    __syncthreads();
    if (tick[0] == GRID - 1) {
        __threadfence();
        float part = 0.0f;
        for (int i = tid; i < CC * DD; i += THREADS) {
            float s = 0.0f;
            #pragma unroll
            for (int r = 0; r < NREP; r++) { s += g_S[r][i]; g_S[r][i] = 0.0f; }
            int   c   = i >> 7;
            int   cnt = g_count[c];
            float cen = centers[i];
            out[1 + i] = (cnt > 0) ? (cen - __fdividef(s, (float)cnt)) : 0.0f;
            part += cen * ((float)cnt * cen - 2.0f * s);   // loss cross terms
        }
        #pragma unroll
        for (int o = 16; o > 0; o >>= 1)
            part += __shfl_xor_sync(0xffffffffu, part, o);
        if (lane == 0) wred[wid] = part;
        __syncthreads();
        if (tid == 0) {
            float t = 0.0f;
            #pragma unroll
            for (int w = 0; w < NWARP; w++) t += wred[w];
            out[0] = (g_loss + t) / 33554432.0f;           // / (N*D)
            g_loss = 0.0f; g_done = 0u;
        }
        if (tid < CC) g_count[tid] = 0;
    }
}

extern "C" void kernel_launch(void* const* d_in, const int* in_sizes, int n_in,
                              void* d_out, int out_size) {
    const float* feature = 0;
    const int*   label   = 0;
    const float* centers = 0;
    for (int i = 0; i < n_in; i++) {
        if (in_sizes[i] == BB * DD * TT)      feature = (const float*)d_in[i];
        else if (in_sizes[i] == BB * TT)      label   = (const int*)d_in[i];
        else if (in_sizes[i] == CC * DD)      centers = (const float*)d_in[i];
    }
    float* out = (float*)d_out;
    (void)out_size;

    cudaFuncSetAttribute(cl_fused_kernel,
                         cudaFuncAttributeMaxDynamicSharedMemorySize, SM_TOTAL);

    cl_fused_kernel<<<GRID, THREADS, SM_TOTAL>>>(feature, label, centers, out);
}